// round 7
// baseline (speedup 1.0000x reference)
#include <cuda_runtime.h>
#include <cstdint>

#define GRID_D 128
#define NUM_CELLS (128*128*128)          // 2,097,152
#define INV_CELL 64.0f
#define MAX_N 1000000

// scan: 4 cells/thread, 256 threads/block -> 1024 cells/block, 2048 blocks
#define SC_THREADS 256
#define SC_PER 4
#define SC_CELLS_PER_BLOCK (SC_THREADS * SC_PER)       // 1024
#define SC_BLOCKS (NUM_CELLS / SC_CELLS_PER_BLOCK)     // 2048

// ---- scratch (device globals; zero-initialized at module load) ----
__device__ __align__(16) unsigned int g_cnt[NUM_CELLS];        // counts -> cursor (re-zeroed by gather)
__device__ __align__(16) unsigned int g_start[NUM_CELLS + 4];  // exclusive scan (+ total)
__device__ unsigned int g_bsums[SC_BLOCKS];
__device__ float4       g_rec[2 * MAX_N];  // {r.xyz, m}, {m*v.xyz, 0} : 32B/particle

// ---------------- K1: per-cell particle counts (4 particles/thread) ------------
__global__ __launch_bounds__(256) void count_kernel(const float4* __restrict__ pos4, int n)
{
    int t = blockIdx.x * blockDim.x + threadIdx.x;
    int base = t * 4;
    if (base >= n) return;
    float px[4], py[4], pz[4];
    if (base + 4 <= n) {
        float4 p0 = pos4[3*t+0], p1 = pos4[3*t+1], p2 = pos4[3*t+2];
        px[0]=p0.x; py[0]=p0.y; pz[0]=p0.z;
        px[1]=p0.w; py[1]=p1.x; pz[1]=p1.y;
        px[2]=p1.z; py[2]=p1.w; pz[2]=p2.x;
        px[3]=p2.y; py[3]=p2.z; pz[3]=p2.w;
#pragma unroll
        for (int k = 0; k < 4; k++) {
            int ix = (int)floorf(px[k]*INV_CELL);
            int iy = (int)floorf(py[k]*INV_CELL);
            int iz = (int)floorf(pz[k]*INV_CELL);
            atomicAdd(&g_cnt[iz + ix*GRID_D + iy*(GRID_D*GRID_D)], 1u);
        }
    } else {
        const float* pos = (const float*)pos4;
        for (int i = base; i < n; i++) {
            int ix = (int)floorf(pos[3*i+0]*INV_CELL);
            int iy = (int)floorf(pos[3*i+1]*INV_CELL);
            int iz = (int)floorf(pos[3*i+2]*INV_CELL);
            atomicAdd(&g_cnt[iz + ix*GRID_D + iy*(GRID_D*GRID_D)], 1u);
        }
    }
}

// ---------------- S1: block sums ----------------
__global__ __launch_bounds__(SC_THREADS) void scanA_kernel()
{
    int tid = threadIdx.x;
    int base = blockIdx.x * SC_CELLS_PER_BLOCK + tid * SC_PER;
    uint4 a = *(const uint4*)(g_cnt + base);
    unsigned s = a.x + a.y + a.z + a.w;
#pragma unroll
    for (int o = 16; o > 0; o >>= 1) s += __shfl_down_sync(0xffffffffu, s, o);
    __shared__ unsigned ws[SC_THREADS / 32];
    if ((tid & 31) == 0) ws[tid >> 5] = s;
    __syncthreads();
    if (tid < 32) {
        unsigned v = (tid < SC_THREADS/32) ? ws[tid] : 0u;
#pragma unroll
        for (int o = 4; o > 0; o >>= 1) v += __shfl_down_sync(0xffffffffu, v, o);
        if (tid == 0) g_bsums[blockIdx.x] = v;
    }
}

// ---------------- S2: exclusive scan of 2048 block sums (one block) -------------
__global__ __launch_bounds__(1024) void scanB_kernel()
{
    int t = threadIdx.x;                   // 0..1023; 2 sums/thread
    unsigned v0 = g_bsums[2*t + 0];
    unsigned v1 = g_bsums[2*t + 1];
    unsigned tsum = v0 + v1;
    unsigned x = tsum;
#pragma unroll
    for (int o = 1; o < 32; o <<= 1) {
        unsigned y = __shfl_up_sync(0xffffffffu, x, o);
        if ((t & 31) >= o) x += y;
    }
    __shared__ unsigned ws[32];
    if ((t & 31) == 31) ws[t >> 5] = x;
    __syncthreads();
    if (t < 32) {
        unsigned w = ws[t];
#pragma unroll
        for (int o = 1; o < 32; o <<= 1) {
            unsigned y = __shfl_up_sync(0xffffffffu, w, o);
            if (t >= o) w += y;
        }
        ws[t] = w;
    }
    __syncthreads();
    unsigned incl = x + ((t >= 32) ? ws[(t >> 5) - 1] : 0u);
    unsigned excl = incl - tsum;
    g_bsums[2*t + 0] = excl;
    g_bsums[2*t + 1] = excl + v0;
    if (t == 1023) g_start[NUM_CELLS] = incl;  // total
}

// ---------------- S3: per-block scan; write starts + scatter cursors ------------
__global__ __launch_bounds__(SC_THREADS) void scanC_kernel()
{
    int tid = threadIdx.x;
    int base = blockIdx.x * SC_CELLS_PER_BLOCK + tid * SC_PER;
    uint4 a = *(const uint4*)(g_cnt + base);
    unsigned c0 = 0, c1 = a.x, c2 = a.x + a.y, c3 = a.x + a.y + a.z;
    unsigned tsum = c3 + a.w;
    unsigned x = tsum;
#pragma unroll
    for (int o = 1; o < 32; o <<= 1) {
        unsigned y = __shfl_up_sync(0xffffffffu, x, o);
        if ((tid & 31) >= o) x += y;
    }
    __shared__ unsigned ws[8], wso[8];
    if ((tid & 31) == 31) ws[tid >> 5] = x;
    __syncthreads();
    if (tid < 8) {
        unsigned w = ws[tid];
#pragma unroll
        for (int o = 1; o < 8; o <<= 1) {
            unsigned y = __shfl_up_sync(0xffu, w, o);
            if (tid >= o) w += y;
        }
        wso[tid] = w;
    }
    __syncthreads();
    unsigned warp_off = (tid >= 32) ? wso[(tid >> 5) - 1] : 0u;
    unsigned excl = (x - tsum) + warp_off + g_bsums[blockIdx.x];
    uint4 o0 = make_uint4(excl + c0, excl + c1, excl + c2, excl + c3);
    *(uint4*)(g_start + base) = o0;
    *(uint4*)(g_cnt + base)   = o0;   // scatter cursor
}

// ---------------- K3: scatter records into cell-sorted order (4/thread) ---------
__global__ __launch_bounds__(256) void scatter_kernel(
    const float4* __restrict__ pos4,
    const float4* __restrict__ vel4,
    const float4* __restrict__ mass4,
    int n)
{
    int t = blockIdx.x * blockDim.x + threadIdx.x;
    int base = t * 4;
    if (base >= n) return;
    float px[4], py[4], pz[4], vx[4], vy[4], vz[4], m[4];
    if (base + 4 <= n) {
        float4 p0 = pos4[3*t+0], p1 = pos4[3*t+1], p2 = pos4[3*t+2];
        px[0]=p0.x; py[0]=p0.y; pz[0]=p0.z;
        px[1]=p0.w; py[1]=p1.x; pz[1]=p1.y;
        px[2]=p1.z; py[2]=p1.w; pz[2]=p2.x;
        px[3]=p2.y; py[3]=p2.z; pz[3]=p2.w;
        float4 v0 = vel4[3*t+0], v1 = vel4[3*t+1], v2 = vel4[3*t+2];
        vx[0]=v0.x; vy[0]=v0.y; vz[0]=v0.z;
        vx[1]=v0.w; vy[1]=v1.x; vz[1]=v1.y;
        vx[2]=v1.z; vy[2]=v1.w; vz[2]=v2.x;
        vx[3]=v2.y; vy[3]=v2.z; vz[3]=v2.w;
        float4 mm = mass4[t];
        m[0]=mm.x; m[1]=mm.y; m[2]=mm.z; m[3]=mm.w;
#pragma unroll
        for (int k = 0; k < 4; k++) {
            float rx = px[k]*INV_CELL, ry = py[k]*INV_CELL, rz = pz[k]*INV_CELL;
            int ix=(int)floorf(rx), iy=(int)floorf(ry), iz=(int)floorf(rz);
            int cell = iz + ix*GRID_D + iy*(GRID_D*GRID_D);
            unsigned idx = atomicAdd(&g_cnt[cell], 1u);
            float mk = m[k];
            g_rec[2*idx + 0] = make_float4(rx, ry, rz, mk);
            g_rec[2*idx + 1] = make_float4(mk*vx[k], mk*vy[k], mk*vz[k], 0.0f);
        }
    } else {
        const float* pos = (const float*)pos4;
        const float* vel = (const float*)vel4;
        const float* mass = (const float*)mass4;
        for (int i = base; i < n; i++) {
            float rx = pos[3*i+0]*INV_CELL, ry = pos[3*i+1]*INV_CELL, rz = pos[3*i+2]*INV_CELL;
            int ix=(int)floorf(rx), iy=(int)floorf(ry), iz=(int)floorf(rz);
            int cell = iz + ix*GRID_D + iy*(GRID_D*GRID_D);
            unsigned idx = atomicAdd(&g_cnt[cell], 1u);
            float mk = mass[i];
            g_rec[2*idx + 0] = make_float4(rx, ry, rz, mk);
            g_rec[2*idx + 1] = make_float4(mk*vel[3*i+0], mk*vel[3*i+1], mk*vel[3*i+2], 0.0f);
        }
    }
}

// ---------------- K4: per-cell gather (no atomics) + scratch re-zero ------------
__global__ __launch_bounds__(256) void gather_kernel(float4* __restrict__ out)
{
    int t = blockIdx.x * blockDim.x + threadIdx.x;   // cell hash; warp = 32 consecutive z
    int cz = t & (GRID_D - 1);
    int cx = (t >> 7) & (GRID_D - 1);
    int cy = t >> 14;
    float fcx = (float)cx, fcy = (float)cy, fcz = (float)cz;

    float am = 0.f, a0 = 0.f, a1 = 0.f, a2 = 0.f;

#pragma unroll
    for (int dx = -1; dx <= 0; dx++) {
#pragma unroll
        for (int dy = -1; dy <= 0; dy++) {
            int h = (cz - 1) + (cx + dx) * GRID_D + (cy + dy) * (GRID_D * GRID_D);
            int lo_i = min(max(h,     0), NUM_CELLS);
            int hi_i = min(max(h + 2, 0), NUM_CELLS);
            unsigned lo = g_start[lo_i];
            unsigned hi = g_start[hi_i];
            for (unsigned j = lo; j < hi; j++) {
                float4 a = g_rec[2*j + 0];
                float4 b = g_rec[2*j + 1];
                float wx = fmaxf(0.0f, 1.0f - fabsf(a.x - fcx));
                float wy = fmaxf(0.0f, 1.0f - fabsf(a.y - fcy));
                float wz = fmaxf(0.0f, 1.0f - fabsf(a.z - fcz));
                float w = wx * wy * wz;
                am = fmaf(w, a.w, am);
                a0 = fmaf(w, b.x, a0);
                a1 = fmaf(w, b.y, a1);
                a2 = fmaf(w, b.z, a2);
            }
        }
    }
    out[t] = make_float4(am, a0, a1, a2);
    g_cnt[t] = 0u;   // re-zero counts for next graph replay (fold memset here)
}

extern "C" void kernel_launch(void* const* d_in, const int* in_sizes, int n_in,
                              void* d_out, int out_size)
{
    const float4* pos4  = (const float4*)d_in[0];
    const float4* vel4  = (const float4*)d_in[1];
    const float4* mass4 = (const float4*)d_in[2];
    int n = in_sizes[2];

    int threads = 256;
    int pblocks = ((n + 3) / 4 + threads - 1) / threads;

    count_kernel  <<<pblocks, threads>>>(pos4, n);
    scanA_kernel  <<<SC_BLOCKS, SC_THREADS>>>();
    scanB_kernel  <<<1, 1024>>>();
    scanC_kernel  <<<SC_BLOCKS, SC_THREADS>>>();
    scatter_kernel<<<pblocks, threads>>>(pos4, vel4, mass4, n);
    gather_kernel <<<NUM_CELLS / 256, 256>>>((float4*)d_out);
}

// round 8
// speedup vs baseline: 2.3467x; 2.3467x over previous
#include <cuda_runtime.h>
#include <cstdint>

#define GRID_D 128
#define NUM_CELLS (128*128*128)
#define INV_CELL 64.0f

// 8 lanes per particle: sub = lane&7 -> (dk = sub>>2) z-corner, (comp = sub&3)
// output component. Each lane issues 4 scalar red.global.add.f32 (one per
// (di,dj) column). Within one RED warp-instruction, the 8 lanes of a particle
// cover 32 CONTIGUOUS bytes of out (cells h and h+1, 4 floats each), so a
// 32-lane instruction touches only ~4-6 L2 sectors -> wavefronts spread
// across instructions (cross-instruction ~1 cyc/wf) instead of ~24-32
// replayed wavefronts inside one RED.v4 (within-instruction ~2 cyc/wf).
__global__ __launch_bounds__(256) void p2g_kernel(
    const float* __restrict__ pos,
    const float* __restrict__ vel,
    const float* __restrict__ mass,
    float* __restrict__ out,
    int n)
{
    int t = blockIdx.x * blockDim.x + threadIdx.x;
    int p    = t >> 3;        // particle index
    int sub  = t & 7;
    int dk   = sub >> 2;      // z-corner (0/1)
    int comp = sub & 3;       // output component (m, mvx, mvy, mvz)
    if (p >= n) return;

    // position in cell units (all 8 lanes load the same particle: coalesced dup)
    float rx = pos[3 * p + 0] * INV_CELL;
    float ry = pos[3 * p + 1] * INV_CELL;
    float rz = pos[3 * p + 2] * INV_CELL;

    float bx = floorf(rx), by = floorf(ry), bz = floorf(rz);
    int ix = (int)bx, iy = (int)by, iz = (int)bz;

    float fx = rx - bx, fy = ry - by, fz = rz - bz;
    float wx[2] = {1.0f - fx, fx};
    float wy[2] = {1.0f - fy, fy};
    float wzk   = dk ? fz : (1.0f - fz);

    float m = mass[p];
    float base;
    if (comp == 0)      base = m;
    else                base = m * vel[3 * p + (comp - 1)];

    // hash of this lane's z-corner
    int h0 = (iz + dk) + ix * GRID_D + iy * (GRID_D * GRID_D);
    float wbase = wzk * base;

#pragma unroll
    for (int di = 0; di < 2; di++) {
#pragma unroll
        for (int dj = 0; dj < 2; dj++) {
            float a = wx[di] * wy[dj] * wbase;
            int h = h0 + di * GRID_D + dj * (GRID_D * GRID_D);
            if ((unsigned)h < (unsigned)NUM_CELLS) {
                float* ptr = out + 4ull * (unsigned)h + comp;
                asm volatile(
                    "red.global.add.f32 [%0], %1;"
                    :: "l"(ptr), "f"(a)
                    : "memory");
            }
        }
    }
}

extern "C" void kernel_launch(void* const* d_in, const int* in_sizes, int n_in,
                              void* d_out, int out_size)
{
    const float* pos  = (const float*)d_in[0];
    const float* vel  = (const float*)d_in[1];
    const float* mass = (const float*)d_in[2];
    float* out = (float*)d_out;
    int n = in_sizes[2];   // NUM_POINTS

    cudaMemsetAsync(d_out, 0, (size_t)out_size * sizeof(float));

    int threads = 256;
    long long total = 8LL * n;               // 8 lanes per particle
    int blocks = (int)((total + threads - 1) / threads);
    p2g_kernel<<<blocks, threads>>>(pos, vel, mass, out, n);
}

// round 9
// speedup vs baseline: 2.3705x; 1.0101x over previous
#include <cuda_runtime.h>
#include <cstdint>

#define GRID_D 128
#define NUM_CELLS (128*128*128)
#define INV_CELL 64.0f

// 4 lanes per particle: dk = (lane>>1)&1 selects the z-corner, cp = lane&1
// selects the component pair ({m, m*vx} or {m*vy, m*vz}). Each lane issues 4
// red.global.add.v2.f32 (one per (di,dj) column). Within one RED
// warp-instruction the 4 lanes of a particle cover 32 CONTIGUOUS bytes of out
// (cells h and h+1), keeping the low per-instruction sector count of the
// scalar variant while halving thread count, redundant ALU, and RED issue.
// No bounds guard: setup guarantees particles are >=1 cell from the boundary,
// so all 8 corner hashes are in range by construction.
__global__ __launch_bounds__(256) void p2g_kernel(
    const float* __restrict__ pos,
    const float* __restrict__ vel,
    const float* __restrict__ mass,
    float* __restrict__ out,
    int n)
{
    int t = blockIdx.x * blockDim.x + threadIdx.x;
    int p  = t >> 2;          // particle index
    int dk = (t >> 1) & 1;    // z-corner
    int cp = t & 1;           // component pair: 0 -> {m, m*vx}, 1 -> {m*vy, m*vz}
    if (p >= n) return;

    float rx = pos[3 * p + 0] * INV_CELL;
    float ry = pos[3 * p + 1] * INV_CELL;
    float rz = pos[3 * p + 2] * INV_CELL;

    float bx = floorf(rx), by = floorf(ry), bz = floorf(rz);
    int ix = (int)bx, iy = (int)by, iz = (int)bz;

    float fx = rx - bx, fy = ry - by, fz = rz - bz;
    float wx[2] = {1.0f - fx, fx};
    float wy[2] = {1.0f - fy, fy};
    float wzk   = dk ? fz : (1.0f - fz);

    float m = mass[p];
    float c0, c1;
    if (cp == 0) { c0 = m;                  c1 = m * vel[3 * p + 0]; }
    else         { c0 = m * vel[3 * p + 1]; c1 = m * vel[3 * p + 2]; }
    c0 *= wzk;
    c1 *= wzk;

    // this lane's base target: cell (ix, iy, iz+dk), component pair cp
    int h0 = (iz + dk) + ix * GRID_D + iy * (GRID_D * GRID_D);
    float* base_ptr = out + 4ull * (unsigned)h0 + 2 * cp;

#pragma unroll
    for (int di = 0; di < 2; di++) {
#pragma unroll
        for (int dj = 0; dj < 2; dj++) {
            float w = wx[di] * wy[dj];
            float a0 = w * c0;
            float a1 = w * c1;
            float* ptr = base_ptr + 4ull * (di * GRID_D + dj * (GRID_D * GRID_D));
            asm volatile(
                "red.global.add.v2.f32 [%0], {%1, %2};"
                :: "l"(ptr), "f"(a0), "f"(a1)
                : "memory");
        }
    }
}

extern "C" void kernel_launch(void* const* d_in, const int* in_sizes, int n_in,
                              void* d_out, int out_size)
{
    const float* pos  = (const float*)d_in[0];
    const float* vel  = (const float*)d_in[1];
    const float* mass = (const float*)d_in[2];
    float* out = (float*)d_out;
    int n = in_sizes[2];   // NUM_POINTS

    cudaMemsetAsync(d_out, 0, (size_t)out_size * sizeof(float));

    int threads = 256;
    long long total = 4LL * n;               // 4 lanes per particle
    int blocks = (int)((total + threads - 1) / threads);
    p2g_kernel<<<blocks, threads>>>(pos, vel, mass, out, n);
}

// round 10
// speedup vs baseline: 2.3929x; 1.0094x over previous
#include <cuda_runtime.h>
#include <cstdint>

#define GRID_D 128
#define NUM_CELLS (128*128*128)
#define INV_CELL 64.0f

// ---------------- zero kernel: 32B stores, leaves out resident in L2 ---------
// 2M cells * 16B = 32MB. Each thread zeroes 64B (2 x v8.b32 256-bit stores).
__global__ __launch_bounds__(256) void zero_kernel(float4* __restrict__ out)
{
    int t = blockIdx.x * blockDim.x + threadIdx.x;   // 512K threads, 64B each
    float4* p = out + 4ull * t;
    float4 z = make_float4(0.f, 0.f, 0.f, 0.f);
    asm volatile(
        "st.global.v8.b32 [%0], {%1,%1,%1,%1,%1,%1,%1,%1};"
        :: "l"(p), "r"(0) : "memory");
    asm volatile(
        "st.global.v8.b32 [%0], {%1,%1,%1,%1,%1,%1,%1,%1};"
        :: "l"(p + 2), "r"(0) : "memory");
    (void)z;
}

// 4 lanes per particle: dk = (lane>>1)&1 selects the z-corner, cp = lane&1
// selects the component pair ({m, m*vx} or {m*vy, m*vz}). Each lane issues 4
// red.global.add.v2.f32 (one per (di,dj) column); the 4 lanes of a particle
// cover 32 contiguous bytes of out per RED warp-instruction. Kernel is pinned
// at the L2 atomic-RMW sector floor (~6M 32B sector-RMWs); SM-side mapping is
// irrelevant beyond keeping sectors contiguous.
__global__ __launch_bounds__(256) void p2g_kernel(
    const float* __restrict__ pos,
    const float* __restrict__ vel,
    const float* __restrict__ mass,
    float* __restrict__ out,
    int n)
{
    int t = blockIdx.x * blockDim.x + threadIdx.x;
    int p  = t >> 2;          // particle index
    int dk = (t >> 1) & 1;    // z-corner
    int cp = t & 1;           // component pair
    if (p >= n) return;

    float rx = pos[3 * p + 0] * INV_CELL;
    float ry = pos[3 * p + 1] * INV_CELL;
    float rz = pos[3 * p + 2] * INV_CELL;

    float bx = floorf(rx), by = floorf(ry), bz = floorf(rz);
    int ix = (int)bx, iy = (int)by, iz = (int)bz;

    float fx = rx - bx, fy = ry - by, fz = rz - bz;
    float wx[2] = {1.0f - fx, fx};
    float wy[2] = {1.0f - fy, fy};
    float wzk   = dk ? fz : (1.0f - fz);

    float m = mass[p];
    float c0, c1;
    if (cp == 0) { c0 = m;                  c1 = m * vel[3 * p + 0]; }
    else         { c0 = m * vel[3 * p + 1]; c1 = m * vel[3 * p + 2]; }
    c0 *= wzk;
    c1 *= wzk;

    int h0 = (iz + dk) + ix * GRID_D + iy * (GRID_D * GRID_D);
    float* base_ptr = out + 4ull * (unsigned)h0 + 2 * cp;

#pragma unroll
    for (int di = 0; di < 2; di++) {
#pragma unroll
        for (int dj = 0; dj < 2; dj++) {
            float w = wx[di] * wy[dj];
            float a0 = w * c0;
            float a1 = w * c1;
            float* ptr = base_ptr + 4ull * (di * GRID_D + dj * (GRID_D * GRID_D));
            asm volatile(
                "red.global.add.v2.f32 [%0], {%1, %2};"
                :: "l"(ptr), "f"(a0), "f"(a1)
                : "memory");
        }
    }
}

extern "C" void kernel_launch(void* const* d_in, const int* in_sizes, int n_in,
                              void* d_out, int out_size)
{
    const float* pos  = (const float*)d_in[0];
    const float* vel  = (const float*)d_in[1];
    const float* mass = (const float*)d_in[2];
    float* out = (float*)d_out;
    int n = in_sizes[2];   // NUM_POINTS

    // zero 32MB output with wide stores (stays L2-resident for the atomics)
    zero_kernel<<<NUM_CELLS / (4 * 256), 256>>>((float4*)out);

    int threads = 256;
    long long total = 4LL * n;               // 4 lanes per particle
    int blocks = (int)((total + threads - 1) / threads);
    p2g_kernel<<<blocks, threads>>>(pos, vel, mass, out, n);
}

// round 11
// speedup vs baseline: 2.4667x; 1.0308x over previous
#include <cuda_runtime.h>
#include <cstdint>

#define GRID_D 128
#define NUM_CELLS (128*128*128)
#define INV_CELL 64.0f

// ---------------- zero kernel: 32B stores, leaves out resident in L2 ---------
// 2M cells * 16B = 32MB. Each thread zeroes 64B (2 x v8.b32 256-bit stores).
// Triggers programmatic launch completion so the p2g kernel can begin its
// (output-independent) prologue while this kernel drains.
__global__ __launch_bounds__(256) void zero_kernel(float4* __restrict__ out)
{
    int t = blockIdx.x * blockDim.x + threadIdx.x;   // 512K threads, 64B each
    float4* p = out + 4ull * t;
    asm volatile(
        "st.global.v8.b32 [%0], {%1,%1,%1,%1,%1,%1,%1,%1};"
        :: "l"(p), "r"(0) : "memory");
    asm volatile(
        "st.global.v8.b32 [%0], {%1,%1,%1,%1,%1,%1,%1,%1};"
        :: "l"(p + 2), "r"(0) : "memory");
    cudaTriggerProgrammaticLaunchCompletion();
}

// 4 lanes per particle: dk = (lane>>1)&1 selects the z-corner, cp = lane&1
// selects the component pair ({m, m*vx} or {m*vy, m*vz}). Each lane issues 4
// red.global.add.v2.f32; the 4 lanes of a particle cover 32 contiguous bytes
// of out per RED warp-instruction. Kernel is pinned at the L2 atomic-sector
// floor (~6M 32B sector-RMWs). All loads + arithmetic run BEFORE the grid
// dependency sync so they overlap the zero kernel's tail (PDL).
__global__ __launch_bounds__(256) void p2g_kernel(
    const float* __restrict__ pos,
    const float* __restrict__ vel,
    const float* __restrict__ mass,
    float* __restrict__ out,
    int n)
{
    int t = blockIdx.x * blockDim.x + threadIdx.x;
    int p  = t >> 2;          // particle index
    int dk = (t >> 1) & 1;    // z-corner
    int cp = t & 1;           // component pair
    if (p >= n) {
        cudaGridDependencySynchronize();
        return;
    }

    float rx = pos[3 * p + 0] * INV_CELL;
    float ry = pos[3 * p + 1] * INV_CELL;
    float rz = pos[3 * p + 2] * INV_CELL;

    float bx = floorf(rx), by = floorf(ry), bz = floorf(rz);
    int ix = (int)bx, iy = (int)by, iz = (int)bz;

    float fx = rx - bx, fy = ry - by, fz = rz - bz;
    float wx[2] = {1.0f - fx, fx};
    float wy[2] = {1.0f - fy, fy};
    float wzk   = dk ? fz : (1.0f - fz);

    float m = mass[p];
    float c0, c1;
    if (cp == 0) { c0 = m;                  c1 = m * vel[3 * p + 0]; }
    else         { c0 = m * vel[3 * p + 1]; c1 = m * vel[3 * p + 2]; }
    c0 *= wzk;
    c1 *= wzk;

    int h0 = (iz + dk) + ix * GRID_D + iy * (GRID_D * GRID_D);
    float* base_ptr = out + 4ull * (unsigned)h0 + 2 * cp;

    // pre-compute all 8 payload values so every load/FMA is issued pre-sync
    float w00 = wx[0] * wy[0], w10 = wx[1] * wy[0];
    float w01 = wx[0] * wy[1], w11 = wx[1] * wy[1];
    float a00_0 = w00 * c0, a00_1 = w00 * c1;
    float a10_0 = w10 * c0, a10_1 = w10 * c1;
    float a01_0 = w01 * c0, a01_1 = w01 * c1;
    float a11_0 = w11 * c0, a11_1 = w11 * c1;

    // wait for zero_kernel's memory to be visible, then fire the atomics
    cudaGridDependencySynchronize();

    float* p00 = base_ptr;
    float* p10 = base_ptr + 4ull * GRID_D;
    float* p01 = base_ptr + 4ull * (GRID_D * GRID_D);
    float* p11 = base_ptr + 4ull * (GRID_D + GRID_D * GRID_D);
    asm volatile("red.global.add.v2.f32 [%0], {%1, %2};" :: "l"(p00), "f"(a00_0), "f"(a00_1) : "memory");
    asm volatile("red.global.add.v2.f32 [%0], {%1, %2};" :: "l"(p10), "f"(a10_0), "f"(a10_1) : "memory");
    asm volatile("red.global.add.v2.f32 [%0], {%1, %2};" :: "l"(p01), "f"(a01_0), "f"(a01_1) : "memory");
    asm volatile("red.global.add.v2.f32 [%0], {%1, %2};" :: "l"(p11), "f"(a11_0), "f"(a11_1) : "memory");
}

extern "C" void kernel_launch(void* const* d_in, const int* in_sizes, int n_in,
                              void* d_out, int out_size)
{
    const float* pos  = (const float*)d_in[0];
    const float* vel  = (const float*)d_in[1];
    const float* mass = (const float*)d_in[2];
    float* out = (float*)d_out;
    int n = in_sizes[2];   // NUM_POINTS

    // zero 32MB output with wide stores (stays L2-resident for the atomics)
    zero_kernel<<<NUM_CELLS / (4 * 256), 256>>>((float4*)out);

    // p2g launched with programmatic stream serialization: starts while the
    // zero kernel drains; atomics held back by cudaGridDependencySynchronize.
    int threads = 256;
    long long total = 4LL * n;               // 4 lanes per particle
    int blocks = (int)((total + threads - 1) / threads);

    cudaLaunchConfig_t cfg = {};
    cfg.gridDim  = dim3((unsigned)blocks, 1, 1);
    cfg.blockDim = dim3((unsigned)threads, 1, 1);
    cfg.dynamicSmemBytes = 0;
    cfg.stream = 0;
    cudaLaunchAttribute attrs[1];
    attrs[0].id = cudaLaunchAttributeProgrammaticStreamSerialization;
    attrs[0].val.programmaticStreamSerializationAllowed = 1;
    cfg.attrs = attrs;
    cfg.numAttrs = 1;

    cudaLaunchKernelEx(&cfg, p2g_kernel, pos, vel, mass, out, n);
}